// round 4
// baseline (speedup 1.0000x reference)
#include <cuda_runtime.h>
#include <cuda_fp16.h>

#define B_      4
#define C_      128
#define N_      4096
#define HEADS_  4
#define DHEAD_  32
#define HID_    128
#define OQKV_   384

// Scratch (static device globals — no runtime allocation)
__device__ float g_mean[B_ * N_];
__device__ float g_rstd[B_ * N_];
__device__ float g_attn[B_ * HID_  * N_];   // [b][h*32+d][n]
// Pre-split fp16 QKV (hi/lo pairs; q pre-scaled). Layout [b][o 0..127][n].
__device__ __half g_qh[B_ * HID_ * N_];
__device__ __half g_ql[B_ * HID_ * N_];
__device__ __half g_kh[B_ * HID_ * N_];
__device__ __half g_kl[B_ * HID_ * N_];
__device__ __half g_vh[B_ * HID_ * N_];

// ---------------------------------------------------------------------------
// Kernel 1: per-position LayerNorm statistics over C=128 channels
// ---------------------------------------------------------------------------
__global__ void ln_stats_kernel(const float* __restrict__ x) {
    int idx = blockIdx.x * blockDim.x + threadIdx.x;   // b*N + n
    int b = idx >> 12;
    int n = idx & (N_ - 1);
    const float* xp = x + (size_t)b * C_ * N_ + n;
    float s = 0.f, s2 = 0.f;
#pragma unroll 8
    for (int c = 0; c < C_; c++) {
        float v = xp[(size_t)c * N_];
        s += v; s2 += v * v;
    }
    float m   = s  * (1.0f / C_);
    float var = s2 * (1.0f / C_) - m * m;
    g_mean[idx] = m;
    g_rstd[idx] = rsqrtf(var + 1e-5f);
}

// ---------------------------------------------------------------------------
// Tiled GEMM:  Y[b,o,n] = sum_c W[o,c] * Xn[b,c,n]
// SPLITOUT: write hi/lo fp16 QKV tensors instead of fp32 Y.
// ---------------------------------------------------------------------------
template<int ODIM, bool LN, bool SPLITOUT, bool BIAS>
__global__ __launch_bounds__(256) void gemm_kernel(
    const float* __restrict__ Wm, const float* __restrict__ X,
    float* __restrict__ Y,
    const float* __restrict__ gamma, const float* __restrict__ beta,
    const float* __restrict__ bias)
{
    __shared__ float Ws[32][68];
    __shared__ float Xs[32][68];

    int b  = blockIdx.z;
    int n0 = blockIdx.x * 64;
    int o0 = blockIdx.y * 64;
    int tid = threadIdx.x;
    int tx = tid & 15, ty = tid >> 4;

    float acc[4][4] = {};
    const float* Xb = X + (size_t)b * C_ * N_;

    for (int k0 = 0; k0 < C_; k0 += 32) {
        {
            int ow  = tid >> 2;
            int kk0 = (tid & 3) * 8;
            const float* wp = Wm + (size_t)(o0 + ow) * C_ + k0 + kk0;
#pragma unroll
            for (int t = 0; t < 8; t++) Ws[kk0 + t][ow] = wp[t];
        }
        {
            int kk  = tid >> 3;
            int nx0 = (tid & 7) * 8;
            const float* xp = Xb + (size_t)(k0 + kk) * N_ + n0 + nx0;
            if (LN) {
                float ga = gamma[k0 + kk], be = beta[k0 + kk];
#pragma unroll
                for (int t = 0; t < 8; t++) {
                    int bn = b * N_ + n0 + nx0 + t;
                    Xs[kk][nx0 + t] = (xp[t] - g_mean[bn]) * g_rstd[bn] * ga + be;
                }
            } else {
#pragma unroll
                for (int t = 0; t < 8; t++) Xs[kk][nx0 + t] = xp[t];
            }
        }
        __syncthreads();
#pragma unroll
        for (int kk = 0; kk < 32; kk++) {
            float4 wv = *reinterpret_cast<const float4*>(&Ws[kk][ty * 4]);
            float4 xv = *reinterpret_cast<const float4*>(&Xs[kk][tx * 4]);
            float wa[4] = {wv.x, wv.y, wv.z, wv.w};
            float xa[4] = {xv.x, xv.y, xv.z, xv.w};
#pragma unroll
            for (int r = 0; r < 4; r++)
#pragma unroll
                for (int c = 0; c < 4; c++)
                    acc[r][c] += wa[r] * xa[c];
        }
        __syncthreads();
    }

    const float qscale = 0.17677669529663687f;  // 32^-0.5
#pragma unroll
    for (int r = 0; r < 4; r++) {
        int o = o0 + ty * 4 + r;
        if (SPLITOUT) {
            // segment is uniform per o (block-uniform up to 64-boundary)
            if (o < HID_) {
                size_t base = ((size_t)b * HID_ + o) * N_ + n0 + tx * 4;
#pragma unroll
                for (int c = 0; c < 4; c++) {
                    float v = acc[r][c] * qscale;
                    __half hh = __float2half_rn(v);
                    g_qh[base + c] = hh;
                    g_ql[base + c] = __float2half_rn(v - __half2float(hh));
                }
            } else if (o < 2 * HID_) {
                size_t base = ((size_t)b * HID_ + (o - HID_)) * N_ + n0 + tx * 4;
#pragma unroll
                for (int c = 0; c < 4; c++) {
                    float v = acc[r][c];
                    __half hh = __float2half_rn(v);
                    g_kh[base + c] = hh;
                    g_kl[base + c] = __float2half_rn(v - __half2float(hh));
                }
            } else {
                size_t base = ((size_t)b * HID_ + (o - 2 * HID_)) * N_ + n0 + tx * 4;
#pragma unroll
                for (int c = 0; c < 4; c++)
                    g_vh[base + c] = __float2half_rn(acc[r][c]);
            }
        } else {
            float extra = BIAS ? bias[o] : 0.f;
            float* yp = Y + ((size_t)b * ODIM + o) * N_ + n0 + tx * 4;
#pragma unroll
            for (int c = 0; c < 4; c++) yp[c] = acc[r][c] + extra;
        }
    }
}

// ---------------------------------------------------------------------------
// Flash attention on tensor cores (mma.sync m16n8k16 fp16, fp32 accum).
// i-tile = 128 rows (8 warps x 16), j-tile = 64. Online softmax in registers.
// Q,K hi/lo pre-split (3 MMAs for S); P fp16; V hi only (1 MMA).
// ---------------------------------------------------------------------------
__device__ __forceinline__ void mma16816(float* c, const unsigned* a,
                                         unsigned b0, unsigned b1) {
    asm volatile(
        "mma.sync.aligned.m16n8k16.row.col.f32.f16.f16.f32 "
        "{%0,%1,%2,%3}, {%4,%5,%6,%7}, {%8,%9}, {%0,%1,%2,%3};\n"
        : "+f"(c[0]), "+f"(c[1]), "+f"(c[2]), "+f"(c[3])
        : "r"(a[0]), "r"(a[1]), "r"(a[2]), "r"(a[3]), "r"(b0), "r"(b1));
}

__device__ __forceinline__ unsigned pack_h2(float x, float y) {
    __half2 h = __floats2half2_rn(x, y);
    return *reinterpret_cast<unsigned*>(&h);
}

// smem map (halves). Stage phase: Qh [i][d] pitch 40 at 0, Ql at 5120.
// Loop phase: KH [j][d] pitch 40 at 0, KL at 2560, VH [d][j] pitch 72 at 5120.
// Epilogue: floats [i][d] pitch 33 (8448 halves).
#define KPITCH 40
#define VPITCH 72
#define SM_KL  2560
#define SM_VH  5120
#define SM_HALVES 10240
#define QPITCH 33

__global__ __launch_bounds__(256) void attn_mma_kernel() {
    __shared__ __align__(16) __half SM[SM_HALVES];
    float* SMf = reinterpret_cast<float*>(SM);

    int bh = blockIdx.y;
    int b = bh >> 2, h = bh & 3;
    int i0 = blockIdx.x * 128;
    int tid  = threadIdx.x;
    int wid  = tid >> 5;
    int lane = tid & 31;
    int lq   = lane >> 2;
    int lr   = lane & 3;

    size_t hb = ((size_t)b * HID_ + h * DHEAD_) * N_;
    const __half* qh_b = g_qh + hb;
    const __half* ql_b = g_ql + hb;
    const __half* kh_b = g_kh + hb;
    const __half* kl_b = g_kl + hb;
    const __half* vh_b = g_vh + hb;

    // ---- Stage Q halves into smem: [i][d] pitch 40 -------------------------
#pragma unroll
    for (int t = 0; t < 8; t++) {
        int idx = tid + t * 256;            // 2048 pairs
        int d = idx >> 6, ip = idx & 63;
        int i = 2 * ip;
        __half2 vh2 = *reinterpret_cast<const __half2*>(qh_b + (size_t)d * N_ + i0 + i);
        SM[i * KPITCH + d]       = __low2half(vh2);
        SM[(i + 1) * KPITCH + d] = __high2half(vh2);
        __half2 vl2 = *reinterpret_cast<const __half2*>(ql_b + (size_t)d * N_ + i0 + i);
        SM[5120 + i * KPITCH + d]       = __low2half(vl2);
        SM[5120 + (i + 1) * KPITCH + d] = __high2half(vl2);
    }
    __syncthreads();

    // ---- Build Q fragments for this warp's 16 rows -------------------------
    unsigned aQh[2][4], aQl[2][4];
    {
        int r0 = wid * 16 + lq;
#pragma unroll
        for (int kt = 0; kt < 2; kt++) {
            int d0 = kt * 16 + lr * 2;
#pragma unroll
            for (int f = 0; f < 4; f++) {
                int r = r0 + ((f & 1) ? 8 : 0);
                int d = d0 + ((f & 2) ? 8 : 0);
                aQh[kt][f] = *reinterpret_cast<const unsigned*>(&SM[r * KPITCH + d]);
                aQl[kt][f] = *reinterpret_cast<const unsigned*>(&SM[5120 + r * KPITCH + d]);
            }
        }
    }
    __syncthreads();

    float s[8][4];
    float o[4][4] = {};
    float m0 = -1e30f, m1 = -1e30f, l0 = 0.f, l1 = 0.f;
    const unsigned FULL = 0xffffffffu;

    for (int j0 = 0; j0 < N_; j0 += 64) {
        // ---- Load K/V half tiles ------------------------------------------
#pragma unroll
        for (int t = 0; t < 4; t++) {
            int idx = tid + t * 256;        // 1024 pairs
            int d = idx >> 5, jp = idx & 31;
            int j = 2 * jp;
            __half2 kh2 = *reinterpret_cast<const __half2*>(kh_b + (size_t)d * N_ + j0 + j);
            SM[j * KPITCH + d]       = __low2half(kh2);
            SM[(j + 1) * KPITCH + d] = __high2half(kh2);
            __half2 kl2 = *reinterpret_cast<const __half2*>(kl_b + (size_t)d * N_ + j0 + j);
            SM[SM_KL + j * KPITCH + d]       = __low2half(kl2);
            SM[SM_KL + (j + 1) * KPITCH + d] = __high2half(kl2);
            __half2 vh2 = *reinterpret_cast<const __half2*>(vh_b + (size_t)d * N_ + j0 + j);
            *reinterpret_cast<__half2*>(&SM[SM_VH + d * VPITCH + j]) = vh2;
        }
        __syncthreads();

        // ---- S = Q^T K (16x64 per warp), hi/lo compensated -----------------
#pragma unroll
        for (int nt = 0; nt < 8; nt++) {
            s[nt][0] = s[nt][1] = s[nt][2] = s[nt][3] = 0.f;
        }
#pragma unroll
        for (int kt = 0; kt < 2; kt++) {
            int dbase = kt * 16 + lr * 2;
#pragma unroll
            for (int nt = 0; nt < 8; nt++) {
                int jrow = nt * 8 + lq;
                unsigned bh0 = *reinterpret_cast<const unsigned*>(&SM[jrow * KPITCH + dbase]);
                unsigned bh1 = *reinterpret_cast<const unsigned*>(&SM[jrow * KPITCH + dbase + 8]);
                unsigned bl0 = *reinterpret_cast<const unsigned*>(&SM[SM_KL + jrow * KPITCH + dbase]);
                unsigned bl1 = *reinterpret_cast<const unsigned*>(&SM[SM_KL + jrow * KPITCH + dbase + 8]);
                mma16816(s[nt], aQh[kt], bh0, bh1);
                mma16816(s[nt], aQh[kt], bl0, bl1);
                mma16816(s[nt], aQl[kt], bh0, bh1);
            }
        }

        // ---- Online softmax ------------------------------------------------
        float mx0 = -1e30f, mx1 = -1e30f;
#pragma unroll
        for (int nt = 0; nt < 8; nt++) {
            mx0 = fmaxf(mx0, fmaxf(s[nt][0], s[nt][1]));
            mx1 = fmaxf(mx1, fmaxf(s[nt][2], s[nt][3]));
        }
        mx0 = fmaxf(mx0, __shfl_xor_sync(FULL, mx0, 1));
        mx0 = fmaxf(mx0, __shfl_xor_sync(FULL, mx0, 2));
        mx1 = fmaxf(mx1, __shfl_xor_sync(FULL, mx1, 1));
        mx1 = fmaxf(mx1, __shfl_xor_sync(FULL, mx1, 2));
        float mn0 = fmaxf(m0, mx0), mn1 = fmaxf(m1, mx1);
        float al0 = __expf(m0 - mn0), al1 = __expf(m1 - mn1);
        m0 = mn0; m1 = mn1;

        float sum0 = 0.f, sum1 = 0.f;
#pragma unroll
        for (int nt = 0; nt < 8; nt++) {
            s[nt][0] = __expf(s[nt][0] - m0);
            s[nt][1] = __expf(s[nt][1] - m0);
            s[nt][2] = __expf(s[nt][2] - m1);
            s[nt][3] = __expf(s[nt][3] - m1);
            sum0 += s[nt][0] + s[nt][1];
            sum1 += s[nt][2] + s[nt][3];
        }
        sum0 += __shfl_xor_sync(FULL, sum0, 1);
        sum0 += __shfl_xor_sync(FULL, sum0, 2);
        sum1 += __shfl_xor_sync(FULL, sum1, 1);
        sum1 += __shfl_xor_sync(FULL, sum1, 2);
        l0 = l0 * al0 + sum0;
        l1 = l1 * al1 + sum1;

#pragma unroll
        for (int nt = 0; nt < 4; nt++) {
            o[nt][0] *= al0; o[nt][1] *= al0;
            o[nt][2] *= al1; o[nt][3] *= al1;
        }

        // ---- P (fp16) @ V_hi -> O (16x32 per warp) -------------------------
#pragma unroll
        for (int kt = 0; kt < 4; kt++) {
            unsigned aP[4];
            aP[0] = pack_h2(s[2 * kt][0],     s[2 * kt][1]);
            aP[1] = pack_h2(s[2 * kt][2],     s[2 * kt][3]);
            aP[2] = pack_h2(s[2 * kt + 1][0], s[2 * kt + 1][1]);
            aP[3] = pack_h2(s[2 * kt + 1][2], s[2 * kt + 1][3]);
            int jbase = kt * 16 + lr * 2;
#pragma unroll
            for (int nt = 0; nt < 4; nt++) {
                int drow = nt * 8 + lq;
                unsigned vh0 = *reinterpret_cast<const unsigned*>(&SM[SM_VH + drow * VPITCH + jbase]);
                unsigned vh1 = *reinterpret_cast<const unsigned*>(&SM[SM_VH + drow * VPITCH + jbase + 8]);
                mma16816(o[nt], aP, vh0, vh1);
            }
        }
        __syncthreads();
    }

    // ---- Epilogue: divide by l, transpose via smem, coalesced store --------
    float inv0 = 1.0f / l0, inv1 = 1.0f / l1;
    {
        int r0 = wid * 16 + lq;
#pragma unroll
        for (int nt = 0; nt < 4; nt++) {
            int d = nt * 8 + lr * 2;
            SMf[r0 * QPITCH + d]           = o[nt][0] * inv0;
            SMf[r0 * QPITCH + d + 1]       = o[nt][1] * inv0;
            SMf[(r0 + 8) * QPITCH + d]     = o[nt][2] * inv1;
            SMf[(r0 + 8) * QPITCH + d + 1] = o[nt][3] * inv1;
        }
    }
    __syncthreads();
    float* ob = g_attn + ((size_t)b * HID_ + h * DHEAD_) * N_ + i0;
#pragma unroll
    for (int t = 0; t < 16; t++) {
        int idx = tid + t * 256;            // 4096 elements
        int d = idx >> 7, i = idx & 127;
        ob[(size_t)d * N_ + i] = SMf[i * QPITCH + d];
    }
}

// ---------------------------------------------------------------------------
extern "C" void kernel_launch(void* const* d_in, const int* in_sizes, int n_in,
                              void* d_out, int out_size) {
    const float* x     = (const float*)d_in[0];
    const float* g     = (const float*)d_in[1];
    const float* beta  = (const float*)d_in[2];
    const float* w_qkv = (const float*)d_in[3];
    const float* w_out = (const float*)d_in[4];
    const float* b_out = (const float*)d_in[5];
    float* out = (float*)d_out;

    float* attn_ptr; cudaGetSymbolAddress((void**)&attn_ptr, g_attn);

    ln_stats_kernel<<<(B_ * N_) / 256, 256>>>(x);

    dim3 g2(N_ / 64, OQKV_ / 64, B_);
    gemm_kernel<OQKV_, true, true, false><<<g2, 256>>>(w_qkv, x, nullptr, g, beta, nullptr);

    dim3 g3(N_ / 128, B_ * HEADS_);
    attn_mma_kernel<<<g3, 256>>>();

    dim3 g4(N_ / 64, HID_ / 64, B_);
    gemm_kernel<HID_, false, false, true><<<g4, 256>>>(w_out, attn_ptr, out, nullptr, nullptr, b_out);
}

// round 6
// speedup vs baseline: 1.4588x; 1.4588x over previous
#include <cuda_runtime.h>
#include <cuda_fp16.h>

#define B_      4
#define C_      128
#define N_      4096
#define HEADS_  4
#define DHEAD_  32
#define HID_    128
#define OQKV_   384

typedef unsigned int u32;

// Scratch (static device globals — no runtime allocation)
__device__ float g_mean[B_ * N_];
__device__ float g_rstd[B_ * N_];
__device__ float g_attn[B_ * HID_ * N_];            // [b][h*32+d][n]
// Q,K pre-split fp16 hi/lo, per-position 128B rows: [b][h][n][hi(32)|lo(32)]
__device__ __half g_q2[B_ * HEADS_ * N_ * 64];
__device__ __half g_k2[B_ * HEADS_ * N_ * 64];
// V fp16 (hi only), [b][h*32+d][n]
__device__ __half g_vh[B_ * HID_ * N_];

// ---------------------------------------------------------------------------
// Kernel 1: per-position LayerNorm statistics over C=128 channels
// ---------------------------------------------------------------------------
__global__ void ln_stats_kernel(const float* __restrict__ x) {
    int idx = blockIdx.x * blockDim.x + threadIdx.x;
    int b = idx >> 12;
    int n = idx & (N_ - 1);
    const float* xp = x + (size_t)b * C_ * N_ + n;
    float s = 0.f, s2 = 0.f;
#pragma unroll 8
    for (int c = 0; c < C_; c++) {
        float v = xp[(size_t)c * N_];
        s += v; s2 += v * v;
    }
    float m   = s  * (1.0f / C_);
    float var = s2 * (1.0f / C_) - m * m;
    g_mean[idx] = m;
    g_rstd[idx] = rsqrtf(var + 1e-5f);
}

// ---------------------------------------------------------------------------
// Tiled GEMM. SPLITOUT=true: write q/k 128B hi|lo rows + v fp16.
// ---------------------------------------------------------------------------
template<int ODIM, bool LN, bool SPLITOUT, bool BIAS>
__global__ __launch_bounds__(256) void gemm_kernel(
    const float* __restrict__ Wm, const float* __restrict__ X,
    float* __restrict__ Y,
    const float* __restrict__ gamma, const float* __restrict__ beta,
    const float* __restrict__ bias)
{
    __shared__ float Ws[32][68];
    __shared__ float Xs[32][68];

    int b  = blockIdx.z;
    int n0 = blockIdx.x * 64;
    int o0 = blockIdx.y * 64;
    int tid = threadIdx.x;
    int tx = tid & 15, ty = tid >> 4;

    float acc[4][4] = {};
    const float* Xb = X + (size_t)b * C_ * N_;

    for (int k0 = 0; k0 < C_; k0 += 32) {
        {
            int ow  = tid >> 2;
            int kk0 = (tid & 3) * 8;
            const float* wp = Wm + (size_t)(o0 + ow) * C_ + k0 + kk0;
#pragma unroll
            for (int t = 0; t < 8; t++) Ws[kk0 + t][ow] = wp[t];
        }
        {
            int kk  = tid >> 3;
            int nx0 = (tid & 7) * 8;
            const float* xp = Xb + (size_t)(k0 + kk) * N_ + n0 + nx0;
            if (LN) {
                float ga = gamma[k0 + kk], be = beta[k0 + kk];
#pragma unroll
                for (int t = 0; t < 8; t++) {
                    int bn = b * N_ + n0 + nx0 + t;
                    Xs[kk][nx0 + t] = (xp[t] - g_mean[bn]) * g_rstd[bn] * ga + be;
                }
            } else {
#pragma unroll
                for (int t = 0; t < 8; t++) Xs[kk][nx0 + t] = xp[t];
            }
        }
        __syncthreads();
#pragma unroll
        for (int kk = 0; kk < 32; kk++) {
            float4 wv = *reinterpret_cast<const float4*>(&Ws[kk][ty * 4]);
            float4 xv = *reinterpret_cast<const float4*>(&Xs[kk][tx * 4]);
            float wa[4] = {wv.x, wv.y, wv.z, wv.w};
            float xa[4] = {xv.x, xv.y, xv.z, xv.w};
#pragma unroll
            for (int r = 0; r < 4; r++)
#pragma unroll
                for (int c = 0; c < 4; c++)
                    acc[r][c] += wa[r] * xa[c];
        }
        __syncthreads();
    }

    const float qscale = 0.17677669529663687f;  // 32^-0.5
#pragma unroll
    for (int r = 0; r < 4; r++) {
        int o = o0 + ty * 4 + r;
        if (SPLITOUT) {
            if (o < 2 * HID_) {
                bool isq = (o < HID_);
                int oo = isq ? o : (o - HID_);
                int hh = oo >> 5, dd = oo & 31;
                __half* dst = (isq ? g_q2 : g_k2) +
                              ((size_t)(b * HEADS_ + hh) * N_ + n0 + tx * 4) * 64 + dd;
                float mult = isq ? qscale : 1.0f;
#pragma unroll
                for (int c = 0; c < 4; c++) {
                    float v = acc[r][c] * mult;
                    __half vh = __float2half_rn(v);
                    dst[(size_t)c * 64]      = vh;
                    dst[(size_t)c * 64 + 32] = __float2half_rn(v - __half2float(vh));
                }
            } else {
                size_t base = ((size_t)b * HID_ + (o - 2 * HID_)) * N_ + n0 + tx * 4;
#pragma unroll
                for (int c = 0; c < 4; c++)
                    g_vh[base + c] = __float2half_rn(acc[r][c]);
            }
        } else {
            float extra = BIAS ? bias[o] : 0.f;
            float* yp = Y + ((size_t)b * ODIM + o) * N_ + n0 + tx * 4;
#pragma unroll
            for (int c = 0; c < 4; c++) yp[c] = acc[r][c] + extra;
        }
    }
}

// ---------------------------------------------------------------------------
// Flash attention, mma.sync m16n8k16, no-max softmax, cp.async double buffer.
// CTA: 256 threads (8 warps x 16 i-rows = 128 rows), j-tile = 64.
// ---------------------------------------------------------------------------
__device__ __forceinline__ void mma16816(float* c, const unsigned* a,
                                         unsigned b0, unsigned b1) {
    asm volatile(
        "mma.sync.aligned.m16n8k16.row.col.f32.f16.f16.f32 "
        "{%0,%1,%2,%3}, {%4,%5,%6,%7}, {%8,%9}, {%0,%1,%2,%3};\n"
        : "+f"(c[0]), "+f"(c[1]), "+f"(c[2]), "+f"(c[3])
        : "r"(a[0]), "r"(a[1]), "r"(a[2]), "r"(a[3]), "r"(b0), "r"(b1));
}
__device__ __forceinline__ unsigned pack_h2(float x, float y) {
    __half2 h = __floats2half2_rn(x, y);
    return *reinterpret_cast<unsigned*>(&h);
}
__device__ __forceinline__ void cp_async16(u32 dst, const void* src) {
    asm volatile("cp.async.cg.shared.global [%0], [%1], 16;\n"
                 :: "r"(dst), "l"(src) : "memory");
}
__device__ __forceinline__ void cp_commit() {
    asm volatile("cp.async.commit_group;\n" ::: "memory");
}
__device__ __forceinline__ void cp_wait0() {
    asm volatile("cp.async.wait_group 0;\n" ::: "memory");
}
__device__ __forceinline__ u32 smem_u32(const void* p) {
    u32 a;
    asm("{ .reg .u64 t; cvta.to.shared.u64 t, %1; cvt.u32.u64 %0, t; }"
        : "=r"(a) : "l"(p));
    return a;
}

// smem: buffers of K (64 rows x 144B) + V (32 rows x 144B), double-buffered.
// K buf c at half-index c*6912; V buf c at c*6912 + 4608. Total 13824 halves.
#define KV_HALVES 13824
#define RPITCH 72   // halves per row (144 bytes, 36 words -> conflict-free)

__global__ __launch_bounds__(256) void attn_mma_kernel() {
    __shared__ __align__(16) __half SM[KV_HALVES];
    float* SMf = reinterpret_cast<float*>(SM);

    int bh = blockIdx.y;
    int b = bh >> 2, h = bh & 3;
    int i0 = blockIdx.x * 128;
    int tid  = threadIdx.x;
    int wid  = tid >> 5;
    int lane = tid & 31;
    int lq   = lane >> 2;
    int lr   = lane & 3;

    const __half* qg = g_q2 + ((size_t)(b * HEADS_ + h) * N_ + i0) * 64;
    const __half* kg = g_k2 + (size_t)(b * HEADS_ + h) * N_ * 64;
    const __half* vg = g_vh + ((size_t)b * HID_ + h * DHEAD_) * N_;

    u32 sbase = smem_u32(SM);

    // ---- Q fragments straight from gmem (one-time, 16 u32 loads) -----------
    unsigned aQh[2][4], aQl[2][4];
    {
        int r0 = wid * 16 + lq;
#pragma unroll
        for (int kt = 0; kt < 2; kt++) {
#pragma unroll
            for (int f = 0; f < 4; f++) {
                int r = r0 + ((f & 1) ? 8 : 0);
                int d = kt * 16 + lr * 2 + ((f & 2) ? 8 : 0);
                aQh[kt][f] = *reinterpret_cast<const unsigned*>(qg + (size_t)r * 64 + d);
                aQl[kt][f] = *reinterpret_cast<const unsigned*>(qg + (size_t)r * 64 + d + 32);
            }
        }
    }

    // ---- prefetch tile 0 into buffer 0 -------------------------------------
    {
#pragma unroll
        for (int t = 0; t < 3; t++) {
            int idx = tid + t * 256;
            if (t < 2) {
                int j = idx >> 3, c = idx & 7;
                cp_async16(sbase + (u32)(j * 144 + c * 16),
                           kg + (size_t)j * 64 + c * 8);
            } else {
                int i2 = idx - 512;
                int d = i2 >> 3, c = i2 & 7;
                cp_async16(sbase + (u32)(4608 * 2 + d * 144 + c * 16),
                           vg + (size_t)d * N_ + c * 8);
            }
        }
        cp_commit();
    }

    float s[8][4];
    float o[4][4] = {};
    float L0 = 0.f, L1 = 0.f;
    const unsigned FULL = 0xffffffffu;

    for (int t64 = 0; t64 < 64; t64++) {
        int cur = t64 & 1;
        int kb = cur * 6912;            // K buffer half-index
        int vb = kb + 4608;             // V buffer half-index

        cp_wait0();                     // tile t64 resident
        __syncthreads();                // visible to all; prev compute done

        // ---- prefetch tile t64+1 into the other buffer ---------------------
        if (t64 < 63) {
            int j0n = (t64 + 1) * 64;
            u32 kdst = sbase + (u32)((6912 - kb) * 2);
            u32 vdst = kdst + 4608 * 2;
#pragma unroll
            for (int t = 0; t < 3; t++) {
                int idx = tid + t * 256;
                if (t < 2) {
                    int j = idx >> 3, c = idx & 7;
                    cp_async16(kdst + (u32)(j * 144 + c * 16),
                               kg + (size_t)(j0n + j) * 64 + c * 8);
                } else {
                    int i2 = idx - 512;
                    int d = i2 >> 3, c = i2 & 7;
                    cp_async16(vdst + (u32)(d * 144 + c * 16),
                               vg + (size_t)d * N_ + j0n + c * 8);
                }
            }
            cp_commit();
        }

        // ---- S = Q K^T (hi/lo compensated, 48 MMAs/warp) --------------------
#pragma unroll
        for (int nt = 0; nt < 8; nt++) {
            s[nt][0] = s[nt][1] = s[nt][2] = s[nt][3] = 0.f;
        }
#pragma unroll
        for (int kt = 0; kt < 2; kt++) {
            int dbase = kt * 16 + lr * 2;
#pragma unroll
            for (int nt = 0; nt < 8; nt++) {
                int jrow = nt * 8 + lq;
                const __half* kr = &SM[kb + jrow * RPITCH];
                unsigned bh0 = *reinterpret_cast<const unsigned*>(kr + dbase);
                unsigned bh1 = *reinterpret_cast<const unsigned*>(kr + dbase + 8);
                unsigned bl0 = *reinterpret_cast<const unsigned*>(kr + dbase + 32);
                unsigned bl1 = *reinterpret_cast<const unsigned*>(kr + dbase + 40);
                mma16816(s[nt], aQh[kt], bh0, bh1);
                mma16816(s[nt], aQh[kt], bl0, bl1);
                mma16816(s[nt], aQl[kt], bh0, bh1);
            }
        }

        // ---- no-max softmax: exp + per-thread partial l ---------------------
#pragma unroll
        for (int nt = 0; nt < 8; nt++) {
            s[nt][0] = __expf(s[nt][0]);
            s[nt][1] = __expf(s[nt][1]);
            s[nt][2] = __expf(s[nt][2]);
            s[nt][3] = __expf(s[nt][3]);
            L0 += s[nt][0] + s[nt][1];
            L1 += s[nt][2] + s[nt][3];
        }

        // ---- O += P V^T (16 MMAs/warp) --------------------------------------
#pragma unroll
        for (int kt = 0; kt < 4; kt++) {
            unsigned aP[4];
            aP[0] = pack_h2(s[2 * kt][0],     s[2 * kt][1]);
            aP[1] = pack_h2(s[2 * kt][2],     s[2 * kt][3]);
            aP[2] = pack_h2(s[2 * kt + 1][0], s[2 * kt + 1][1]);
            aP[3] = pack_h2(s[2 * kt + 1][2], s[2 * kt + 1][3]);
            int jbase = kt * 16 + lr * 2;
#pragma unroll
            for (int nt = 0; nt < 4; nt++) {
                int drow = nt * 8 + lq;
                const __half* vr = &SM[vb + drow * RPITCH];
                unsigned vh0 = *reinterpret_cast<const unsigned*>(vr + jbase);
                unsigned vh1 = *reinterpret_cast<const unsigned*>(vr + jbase + 8);
                mma16816(o[nt], aP, vh0, vh1);
            }
        }
    }

    // ---- final l reduction (once) ------------------------------------------
    L0 += __shfl_xor_sync(FULL, L0, 1);
    L0 += __shfl_xor_sync(FULL, L0, 2);
    L1 += __shfl_xor_sync(FULL, L1, 1);
    L1 += __shfl_xor_sync(FULL, L1, 2);
    float inv0 = 1.0f / L0, inv1 = 1.0f / L1;

    // ---- epilogue: normalize, transpose via smem, coalesced store ----------
    __syncthreads();   // buffers dead, reuse as float staging [i][33]
    {
        int r0 = wid * 16 + lq;
#pragma unroll
        for (int nt = 0; nt < 4; nt++) {
            int d = nt * 8 + lr * 2;
            SMf[r0 * 33 + d]           = o[nt][0] * inv0;
            SMf[r0 * 33 + d + 1]       = o[nt][1] * inv0;
            SMf[(r0 + 8) * 33 + d]     = o[nt][2] * inv1;
            SMf[(r0 + 8) * 33 + d + 1] = o[nt][3] * inv1;
        }
    }
    __syncthreads();
    float* ob = g_attn + ((size_t)b * HID_ + h * DHEAD_) * N_ + i0;
#pragma unroll
    for (int t = 0; t < 16; t++) {
        int idx = tid + t * 256;            // 4096 elements
        int d = idx >> 7, i = idx & 127;
        ob[(size_t)d * N_ + i] = SMf[i * 33 + d];
    }
}

// ---------------------------------------------------------------------------
extern "C" void kernel_launch(void* const* d_in, const int* in_sizes, int n_in,
                              void* d_out, int out_size) {
    const float* x     = (const float*)d_in[0];
    const float* g     = (const float*)d_in[1];
    const float* beta  = (const float*)d_in[2];
    const float* w_qkv = (const float*)d_in[3];
    const float* w_out = (const float*)d_in[4];
    const float* b_out = (const float*)d_in[5];
    float* out = (float*)d_out;

    float* attn_ptr; cudaGetSymbolAddress((void**)&attn_ptr, g_attn);

    ln_stats_kernel<<<(B_ * N_) / 256, 256>>>(x);

    dim3 g2(N_ / 64, OQKV_ / 64, B_);
    gemm_kernel<OQKV_, true, true, false><<<g2, 256>>>(w_qkv, x, nullptr, g, beta, nullptr);

    dim3 g3(N_ / 128, B_ * HEADS_);
    attn_mma_kernel<<<g3, 256>>>();

    dim3 g4(N_ / 64, HID_ / 64, B_);
    gemm_kernel<HID_, false, false, true><<<g4, 256>>>(w_out, attn_ptr, out, nullptr, nullptr, b_out);
}

// round 7
// speedup vs baseline: 1.8813x; 1.2896x over previous
#include <cuda_runtime.h>
#include <cuda_fp16.h>

#define B_      4
#define C_      128
#define N_      4096
#define HEADS_  4
#define DHEAD_  32
#define HID_    128
#define OQKV_   384

typedef unsigned int u32;

// Scratch (static device globals — no runtime allocation)
__device__ float g_mean[B_ * N_];
__device__ float g_rstd[B_ * N_];
// LN'd x, per-position rows: [b][n][hi(128)|lo(128)] halves
__device__ __half g_x2[B_ * N_ * 256];
// attention output, per-position rows: [b][n][hi(128)|lo(128)]
__device__ __half g_o2[B_ * N_ * 256];
// weights, hi|lo rows of 256 halves (qscale baked into q rows of w_qkv)
__device__ __half g_w2q[OQKV_ * 256];
__device__ __half g_w2o[HID_ * 256];
// Q,K pre-split fp16 hi/lo, per-position rows: [b][h][n][hi(32)|lo(32)]
__device__ __half g_q2[B_ * HEADS_ * N_ * 64];
__device__ __half g_k2[B_ * HEADS_ * N_ * 64];
// V fp16 (hi only), [b][h*32+d][n]
__device__ __half g_vh[B_ * HID_ * N_];

// ---------------------------------------------------------------------------
__device__ __forceinline__ void mma16816(float* c, const unsigned* a,
                                         unsigned b0, unsigned b1) {
    asm volatile(
        "mma.sync.aligned.m16n8k16.row.col.f32.f16.f16.f32 "
        "{%0,%1,%2,%3}, {%4,%5,%6,%7}, {%8,%9}, {%0,%1,%2,%3};\n"
        : "+f"(c[0]), "+f"(c[1]), "+f"(c[2]), "+f"(c[3])
        : "r"(a[0]), "r"(a[1]), "r"(a[2]), "r"(a[3]), "r"(b0), "r"(b1));
}
__device__ __forceinline__ unsigned pack_h2(float x, float y) {
    __half2 h = __floats2half2_rn(x, y);
    return *reinterpret_cast<unsigned*>(&h);
}
__device__ __forceinline__ void cp_async16(u32 dst, const void* src) {
    asm volatile("cp.async.cg.shared.global [%0], [%1], 16;\n"
                 :: "r"(dst), "l"(src) : "memory");
}
__device__ __forceinline__ void cp_commit() {
    asm volatile("cp.async.commit_group;\n" ::: "memory");
}
__device__ __forceinline__ void cp_wait0() {
    asm volatile("cp.async.wait_group 0;\n" ::: "memory");
}
__device__ __forceinline__ u32 smem_u32(const void* p) {
    u32 a;
    asm("{ .reg .u64 t; cvta.to.shared.u64 t, %1; cvt.u32.u64 %0, t; }"
        : "=r"(a) : "l"(p));
    return a;
}

// ---------------------------------------------------------------------------
// Kernel 1: per-position LayerNorm statistics over C=128 channels
// ---------------------------------------------------------------------------
__global__ void ln_stats_kernel(const float* __restrict__ x) {
    int idx = blockIdx.x * blockDim.x + threadIdx.x;
    int b = idx >> 12;
    int n = idx & (N_ - 1);
    const float* xp = x + (size_t)b * C_ * N_ + n;
    float s = 0.f, s2 = 0.f;
#pragma unroll 8
    for (int c = 0; c < C_; c++) {
        float v = xp[(size_t)c * N_];
        s += v; s2 += v * v;
    }
    float m   = s  * (1.0f / C_);
    float var = s2 * (1.0f / C_) - m * m;
    g_mean[idx] = m;
    g_rstd[idx] = rsqrtf(var + 1e-5f);
}

// ---------------------------------------------------------------------------
// Kernel 1b: weights -> hi|lo fp16 rows (qscale baked into q rows)
// ---------------------------------------------------------------------------
__global__ void w_convert_kernel(const float* __restrict__ w_qkv,
                                 const float* __restrict__ w_out) {
    int row = blockIdx.x;       // 0..511
    int c   = threadIdx.x;      // 0..127
    const float* src;
    __half* dst;
    float scale = 1.0f;
    if (row < OQKV_) {
        src = w_qkv + (size_t)row * C_;
        dst = g_w2q + (size_t)row * 256;
        if (row < HID_) scale = 0.17677669529663687f;   // 32^-0.5
    } else {
        src = w_out + (size_t)(row - OQKV_) * C_;
        dst = g_w2o + (size_t)(row - OQKV_) * 256;
    }
    float v = src[c] * scale;
    __half hh = __float2half_rn(v);
    dst[c]       = hh;
    dst[128 + c] = __float2half_rn(v - __half2float(hh));
}

// ---------------------------------------------------------------------------
// Kernel 1c: apply LN, transpose to per-position rows, split hi/lo
// block: 128 channels x 32 positions
// ---------------------------------------------------------------------------
__global__ __launch_bounds__(256) void x_convert_kernel(
    const float* __restrict__ x,
    const float* __restrict__ gamma, const float* __restrict__ beta) {
    __shared__ float xs[128][33];
    __shared__ float mm[32], rs[32];

    int n0 = blockIdx.x * 32;
    int b  = blockIdx.y;
    int tid = threadIdx.x;

#pragma unroll
    for (int t = 0; t < 16; t++) {
        int idx = tid + t * 256;
        int c = idx >> 5, nn = idx & 31;
        xs[c][nn] = x[((size_t)b * C_ + c) * N_ + n0 + nn];
    }
    if (tid < 32) {
        mm[tid] = g_mean[b * N_ + n0 + tid];
        rs[tid] = g_rstd[b * N_ + n0 + tid];
    }
    __syncthreads();

#pragma unroll
    for (int t = 0; t < 16; t++) {
        int idx = tid + t * 256;
        int nn = idx >> 7, c = idx & 127;
        float v = (xs[c][nn] - mm[nn]) * rs[nn] * gamma[c] + beta[c];
        __half hh = __float2half_rn(v);
        __half* base = g_x2 + ((size_t)(b * N_ + n0 + nn)) * 256;
        base[c]       = hh;
        base[128 + c] = __float2half_rn(v - __half2float(hh));
    }
}

// ---------------------------------------------------------------------------
// Tensor-core GEMM: Y[o, n] = sum_c W[o,c] X[n,c], hi/lo compensated (3 MMA).
// CTA: 256 threads, tile 128 o x 64 n, K = 128 (8 ksteps).
// mode 0: q rows  1: k rows  2: v [d][n]  3: fp32 out + bias
// ---------------------------------------------------------------------------
__global__ __launch_bounds__(256) void tc_gemm_kernel(
    float* __restrict__ outp, const float* __restrict__ bias, int mode_base) {
    __shared__ __align__(16) __half XS[2][64][136];

    int b  = blockIdx.z;
    int n0 = blockIdx.x * 64;
    int mode = mode_base + blockIdx.y;
    const __half* W  = (mode < 3) ? (g_w2q + (size_t)blockIdx.y * HID_ * 256) : g_w2o;
    const __half* Bb = ((mode < 3) ? g_x2 : g_o2) + ((size_t)(b * N_ + n0)) * 256;

    int tid = threadIdx.x;
    int wid = tid >> 5, lane = tid & 31;
    int lq = lane >> 2, lr = lane & 3;

    // stage B rows: 64 x [hi128|lo128] -> XS[0]=hi, XS[1]=lo (pitch 136)
#pragma unroll
    for (int t = 0; t < 8; t++) {
        int idx = tid + t * 256;
        int row = idx >> 5, c16 = idx & 31;
        uint4 v = *reinterpret_cast<const uint4*>(Bb + (size_t)row * 256 + c16 * 8);
        int hl = c16 >> 4, off = (c16 & 15) * 8;
        *reinterpret_cast<uint4*>(&XS[hl][row][off]) = v;
    }
    __syncthreads();

    float s[8][4] = {};
    int r0 = wid * 16 + lq;

#pragma unroll
    for (int ks = 0; ks < 8; ks++) {
        unsigned ah[4], al[4];
#pragma unroll
        for (int f = 0; f < 4; f++) {
            int rr = r0 + ((f & 1) ? 8 : 0);
            int kk = ks * 16 + lr * 2 + ((f & 2) ? 8 : 0);
            ah[f] = *reinterpret_cast<const unsigned*>(W + (size_t)rr * 256 + kk);
            al[f] = *reinterpret_cast<const unsigned*>(W + (size_t)rr * 256 + kk + 128);
        }
#pragma unroll
        for (int nt = 0; nt < 8; nt++) {
            int row = nt * 8 + lq;
            int kk = ks * 16 + lr * 2;
            unsigned bh0 = *reinterpret_cast<const unsigned*>(&XS[0][row][kk]);
            unsigned bh1 = *reinterpret_cast<const unsigned*>(&XS[0][row][kk + 8]);
            unsigned bl0 = *reinterpret_cast<const unsigned*>(&XS[1][row][kk]);
            unsigned bl1 = *reinterpret_cast<const unsigned*>(&XS[1][row][kk + 8]);
            mma16816(s[nt], ah, bh0, bh1);
            mma16816(s[nt], ah, bl0, bl1);
            mma16816(s[nt], al, bh0, bh1);
        }
    }

    // ---- epilogue ----------------------------------------------------------
    if (mode <= 1) {
        __half* base = (mode == 0) ? g_q2 : g_k2;
#pragma unroll
        for (int part = 0; part < 2; part++) {
            int r = r0 + part * 8;
            int h = r >> 5, d = r & 31;
            __half* dst = base + ((size_t)(b * HEADS_ + h) * N_) * 64;
#pragma unroll
            for (int nt = 0; nt < 8; nt++) {
#pragma unroll
                for (int cc = 0; cc < 2; cc++) {
                    int n = n0 + nt * 8 + lr * 2 + cc;
                    float v = s[nt][part * 2 + cc];
                    __half hh = __float2half_rn(v);
                    dst[(size_t)n * 64 + d]      = hh;
                    dst[(size_t)n * 64 + 32 + d] = __float2half_rn(v - __half2float(hh));
                }
            }
        }
    } else if (mode == 2) {
#pragma unroll
        for (int part = 0; part < 2; part++) {
            int r = r0 + part * 8;
            __half* dst = g_vh + ((size_t)(b * HID_ + r)) * N_;
#pragma unroll
            for (int nt = 0; nt < 8; nt++) {
#pragma unroll
                for (int cc = 0; cc < 2; cc++) {
                    int n = n0 + nt * 8 + lr * 2 + cc;
                    dst[n] = __float2half_rn(s[nt][part * 2 + cc]);
                }
            }
        }
    } else {
#pragma unroll
        for (int part = 0; part < 2; part++) {
            int r = r0 + part * 8;
            float bv = bias[r];
            float* dst = outp + ((size_t)(b * HID_ + r)) * N_;
#pragma unroll
            for (int nt = 0; nt < 8; nt++) {
#pragma unroll
                for (int cc = 0; cc < 2; cc++) {
                    int n = n0 + nt * 8 + lr * 2 + cc;
                    dst[n] = s[nt][part * 2 + cc] + bv;
                }
            }
        }
    }
}

// ---------------------------------------------------------------------------
// Flash attention, mma.sync m16n8k16, no-max softmax, cp.async double buffer.
// CTA: 256 threads (8 warps x 16 i-rows = 128 rows), j-tile = 64.
// ---------------------------------------------------------------------------
#define KV_HALVES 13824
#define RPITCH 72

__global__ __launch_bounds__(256) void attn_mma_kernel() {
    __shared__ __align__(16) __half SM[KV_HALVES];
    float* SMf = reinterpret_cast<float*>(SM);

    int bh = blockIdx.y;
    int b = bh >> 2, h = bh & 3;
    int i0 = blockIdx.x * 128;
    int tid  = threadIdx.x;
    int wid  = tid >> 5;
    int lane = tid & 31;
    int lq   = lane >> 2;
    int lr   = lane & 3;

    const __half* qg = g_q2 + ((size_t)(b * HEADS_ + h) * N_ + i0) * 64;
    const __half* kg = g_k2 + (size_t)(b * HEADS_ + h) * N_ * 64;
    const __half* vg = g_vh + ((size_t)b * HID_ + h * DHEAD_) * N_;

    u32 sbase = smem_u32(SM);

    // ---- Q fragments straight from gmem ------------------------------------
    unsigned aQh[2][4], aQl[2][4];
    {
        int r0 = wid * 16 + lq;
#pragma unroll
        for (int kt = 0; kt < 2; kt++) {
#pragma unroll
            for (int f = 0; f < 4; f++) {
                int r = r0 + ((f & 1) ? 8 : 0);
                int d = kt * 16 + lr * 2 + ((f & 2) ? 8 : 0);
                aQh[kt][f] = *reinterpret_cast<const unsigned*>(qg + (size_t)r * 64 + d);
                aQl[kt][f] = *reinterpret_cast<const unsigned*>(qg + (size_t)r * 64 + d + 32);
            }
        }
    }

    // ---- prefetch tile 0 ----------------------------------------------------
    {
#pragma unroll
        for (int t = 0; t < 3; t++) {
            int idx = tid + t * 256;
            if (t < 2) {
                int j = idx >> 3, c = idx & 7;
                cp_async16(sbase + (u32)(j * 144 + c * 16),
                           kg + (size_t)j * 64 + c * 8);
            } else {
                int i2 = idx - 512;
                int d = i2 >> 3, c = i2 & 7;
                cp_async16(sbase + (u32)(4608 * 2 + d * 144 + c * 16),
                           vg + (size_t)d * N_ + c * 8);
            }
        }
        cp_commit();
    }

    float s[8][4];
    float o[4][4] = {};
    float L0 = 0.f, L1 = 0.f;
    const unsigned FULL = 0xffffffffu;

    for (int t64 = 0; t64 < 64; t64++) {
        int cur = t64 & 1;
        int kb = cur * 6912;
        int vb = kb + 4608;

        cp_wait0();
        __syncthreads();

        if (t64 < 63) {
            int j0n = (t64 + 1) * 64;
            u32 kdst = sbase + (u32)((6912 - kb) * 2);
            u32 vdst = kdst + 4608 * 2;
#pragma unroll
            for (int t = 0; t < 3; t++) {
                int idx = tid + t * 256;
                if (t < 2) {
                    int j = idx >> 3, c = idx & 7;
                    cp_async16(kdst + (u32)(j * 144 + c * 16),
                               kg + (size_t)(j0n + j) * 64 + c * 8);
                } else {
                    int i2 = idx - 512;
                    int d = i2 >> 3, c = i2 & 7;
                    cp_async16(vdst + (u32)(d * 144 + c * 16),
                               vg + (size_t)d * N_ + j0n + c * 8);
                }
            }
            cp_commit();
        }

        // ---- S = Q K^T (hi/lo compensated) ---------------------------------
#pragma unroll
        for (int nt = 0; nt < 8; nt++) {
            s[nt][0] = s[nt][1] = s[nt][2] = s[nt][3] = 0.f;
        }
#pragma unroll
        for (int kt = 0; kt < 2; kt++) {
            int dbase = kt * 16 + lr * 2;
#pragma unroll
            for (int nt = 0; nt < 8; nt++) {
                int jrow = nt * 8 + lq;
                const __half* kr = &SM[kb + jrow * RPITCH];
                unsigned bh0 = *reinterpret_cast<const unsigned*>(kr + dbase);
                unsigned bh1 = *reinterpret_cast<const unsigned*>(kr + dbase + 8);
                unsigned bl0 = *reinterpret_cast<const unsigned*>(kr + dbase + 32);
                unsigned bl1 = *reinterpret_cast<const unsigned*>(kr + dbase + 40);
                mma16816(s[nt], aQh[kt], bh0, bh1);
                mma16816(s[nt], aQh[kt], bl0, bl1);
                mma16816(s[nt], aQl[kt], bh0, bh1);
            }
        }

        // ---- no-max softmax -------------------------------------------------
#pragma unroll
        for (int nt = 0; nt < 8; nt++) {
            s[nt][0] = __expf(s[nt][0]);
            s[nt][1] = __expf(s[nt][1]);
            s[nt][2] = __expf(s[nt][2]);
            s[nt][3] = __expf(s[nt][3]);
            L0 += s[nt][0] + s[nt][1];
            L1 += s[nt][2] + s[nt][3];
        }

        // ---- O += P V^T -----------------------------------------------------
#pragma unroll
        for (int kt = 0; kt < 4; kt++) {
            unsigned aP[4];
            aP[0] = pack_h2(s[2 * kt][0],     s[2 * kt][1]);
            aP[1] = pack_h2(s[2 * kt][2],     s[2 * kt][3]);
            aP[2] = pack_h2(s[2 * kt + 1][0], s[2 * kt + 1][1]);
            aP[3] = pack_h2(s[2 * kt + 1][2], s[2 * kt + 1][3]);
            int jbase = kt * 16 + lr * 2;
#pragma unroll
            for (int nt = 0; nt < 4; nt++) {
                int drow = nt * 8 + lq;
                const __half* vr = &SM[vb + drow * RPITCH];
                unsigned vh0 = *reinterpret_cast<const unsigned*>(vr + jbase);
                unsigned vh1 = *reinterpret_cast<const unsigned*>(vr + jbase + 8);
                mma16816(o[nt], aP, vh0, vh1);
            }
        }
    }

    // ---- final l reduction --------------------------------------------------
    L0 += __shfl_xor_sync(FULL, L0, 1);
    L0 += __shfl_xor_sync(FULL, L0, 2);
    L1 += __shfl_xor_sync(FULL, L1, 1);
    L1 += __shfl_xor_sync(FULL, L1, 2);
    float inv0 = 1.0f / L0, inv1 = 1.0f / L1;

    // ---- epilogue: normalize, stage, write hi|lo rows into g_o2 ------------
    __syncthreads();
    {
        int r0 = wid * 16 + lq;
#pragma unroll
        for (int nt = 0; nt < 4; nt++) {
            int d = nt * 8 + lr * 2;
            SMf[r0 * 33 + d]           = o[nt][0] * inv0;
            SMf[r0 * 33 + d + 1]       = o[nt][1] * inv0;
            SMf[(r0 + 8) * 33 + d]     = o[nt][2] * inv1;
            SMf[(r0 + 8) * 33 + d + 1] = o[nt][3] * inv1;
        }
    }
    __syncthreads();
#pragma unroll
    for (int t = 0; t < 16; t++) {
        int idx = tid + t * 256;            // 4096 elements
        int i = idx >> 5, d = idx & 31;
        float v = SMf[i * 33 + d];
        __half hh = __float2half_rn(v);
        __half* rowp = g_o2 + ((size_t)(b * N_ + i0 + i)) * 256 + h * DHEAD_ + d;
        rowp[0]   = hh;
        rowp[128] = __float2half_rn(v - __half2float(hh));
    }
}

// ---------------------------------------------------------------------------
extern "C" void kernel_launch(void* const* d_in, const int* in_sizes, int n_in,
                              void* d_out, int out_size) {
    const float* x     = (const float*)d_in[0];
    const float* g     = (const float*)d_in[1];
    const float* beta  = (const float*)d_in[2];
    const float* w_qkv = (const float*)d_in[3];
    const float* w_out = (const float*)d_in[4];
    const float* b_out = (const float*)d_in[5];
    float* out = (float*)d_out;

    ln_stats_kernel<<<(B_ * N_) / 256, 256>>>(x);
    w_convert_kernel<<<OQKV_ + HID_, 128>>>(w_qkv, w_out);

    dim3 gx(N_ / 32, B_);
    x_convert_kernel<<<gx, 256>>>(x, g, beta);

    dim3 gq(N_ / 64, 3, B_);
    tc_gemm_kernel<<<gq, 256>>>(nullptr, nullptr, 0);

    dim3 ga(N_ / 128, B_ * HEADS_);
    attn_mma_kernel<<<ga, 256>>>();

    dim3 go(N_ / 64, 1, B_);
    tc_gemm_kernel<<<go, 256>>>(out, b_out, 3);
}